// round 15
// baseline (speedup 1.0000x reference)
#include <cuda_runtime.h>
#include <cuda_fp16.h>
#include <math.h>
#include <cstdint>

#define BATCH 256
#define NPTS  1024

// Scratch (device globals — allocation-free contract)
__device__ __half g_H2hi[BATCH * NPTS * 128];   // 64 MB
__device__ __half g_H2lo[BATCH * NPTS * 128];   // 64 MB
__device__ unsigned char g_H2q[BATCH * NPTS * 128];  // 32 MB u8 panel
__device__ float  g_Sc  [BATCH * NPTS];         // per-point scale (rowmax/255)
__device__ float g_G[BATCH * 1024];
__device__ float g_Z1[BATCH * 512];
__device__ float g_Z2[BATCH * 256];
__device__ float g_RAW[BATCH * 9];

extern __shared__ char smem_raw[];

__device__ __forceinline__ uint32_t smem_u32(const void* p) {
    uint32_t a;
    asm("{ .reg .u64 t; cvta.to.shared.u64 t, %1; cvt.u32.u64 %0, t; }" : "=r"(a) : "l"(p));
    return a;
}

#define LDSM_X4(r0, r1, r2, r3, addr) \
    asm volatile("ldmatrix.sync.aligned.m8n8.x4.shared.b16 {%0,%1,%2,%3}, [%4];" \
                 : "=r"(r0), "=r"(r1), "=r"(r2), "=r"(r3) : "r"(addr))

__device__ __forceinline__ void mma_f16(float* d, const uint32_t* a, const uint32_t* b) {
    asm volatile("mma.sync.aligned.m16n8k16.row.col.f32.f16.f16.f32 "
                 "{%0,%1,%2,%3},{%4,%5,%6,%7},{%8,%9},{%0,%1,%2,%3};"
                 : "+f"(d[0]), "+f"(d[1]), "+f"(d[2]), "+f"(d[3])
                 : "r"(a[0]), "r"(a[1]), "r"(a[2]), "r"(a[3]), "r"(b[0]), "r"(b[1]));
}

// u8 x s8 MMA: K=32 per instruction, s32 accumulate
__device__ __forceinline__ void mma_u8s8(int* d, const uint32_t* a, const uint32_t* b) {
    asm volatile("mma.sync.aligned.m16n8k32.row.col.s32.u8.s8.s32 "
                 "{%0,%1,%2,%3},{%4,%5,%6,%7},{%8,%9},{%0,%1,%2,%3};"
                 : "+r"(d[0]), "+r"(d[1]), "+r"(d[2]), "+r"(d[3])
                 : "r"(a[0]), "r"(a[1]), "r"(a[2]), "r"(a[3]), "r"(b[0]), "r"(b[1]));
}

__device__ __forceinline__ uint32_t h2u(__half2 v) {
    uint32_t u; *(__half2*)&u = v; return u;
}

__device__ __forceinline__ void split2(float va, float vb, uint32_t& hi, uint32_t& lo) {
    __half2 h = __floats2half2_rn(va, vb);
    __half2 l = __floats2half2_rn(va - __half2float(__low2half(h)),
                                  vb - __half2float(__high2half(h)));
    hi = h2u(h); lo = h2u(l);
}

#define CP_ASYNC16(dst, src) \
    asm volatile("cp.async.cg.shared.global [%0], [%1], 16;" :: "r"(dst), "l"(src))
#define CP_COMMIT() asm volatile("cp.async.commit_group;" ::: "memory")
#define CP_WAIT(n)  asm volatile("cp.async.wait_group %0;" :: "n"(n) : "memory")

// ---------------------------------------------------------------------------
// K1: per-point MLP 3 -> 64 (scalar) -> 128 (HMMA fp16 3-combo hi/lo, fp32 acc).
// Epilogue: bias+ReLU, hi/lo fp16 split, per-point rowmax, u8 quant panel.
// 64-point CTAs, 256 threads (8 warps, 2m x 4n), 2 CTAs/SM.
// ---------------------------------------------------------------------------
#define K1_LDP 144
#define K1_A_HI 0
#define K1_A_LO 9216
#define K1_B_HI 18432
#define K1_B_LO 36864
#define K1_W1S  55296
#define K1_B1S  56064
#define K1_B2S  56320
#define K1_RM   56832
#define K1_SMEM 57856

__global__ void __launch_bounds__(256, 2) k1_point_mlp(
    const float* __restrict__ x,
    const float* __restrict__ W1, const float* __restrict__ b1,
    const float* __restrict__ W2, const float* __restrict__ b2)
{
    char* sm = smem_raw;
    const uint32_t sb = smem_u32(sm);
    const int tid = threadIdx.x, lane = tid & 31, w = tid >> 5;
    const int wm = w & 1, wn = w >> 1;   // 2m x 4n, warp tile 32x32
    float* W1s = (float*)(sm + K1_W1S);
    float* b1s = (float*)(sm + K1_B1S);
    float* b2s = (float*)(sm + K1_B2S);
    float* rm  = (float*)(sm + K1_RM);   // [4 wn][64 rows]

    for (int i = tid; i < 8192; i += 256) {
        const int n = i & 127, k = i >> 7;
        const float v = W2[k * 128 + n];
        const __half h = __float2half_rn(v);
        const __half l = __float2half_rn(v - __half2float(h));
        *(__half*)(sm + K1_B_HI + n * K1_LDP + k * 2) = h;
        *(__half*)(sm + K1_B_LO + n * K1_LDP + k * 2) = l;
    }
    if (tid < 192) W1s[tid] = W1[tid];
    else           b1s[tid - 192] = b1[tid - 192];
    if (tid < 128) b2s[tid] = b2[tid];
    __syncthreads();

    {
        const int pl = tid & 63;
        const int ks = (tid >> 6) * 16;
        const int pg = blockIdx.x * 64 + pl;
        const float x0 = x[pg * 3 + 0];
        const float x1 = x[pg * 3 + 1];
        const float x2 = x[pg * 3 + 2];
        #pragma unroll
        for (int kk = 0; kk < 16; kk += 2) {
            const int k = ks + kk;
            float va = fmaxf(fmaf(x0, W1s[k],     fmaf(x1, W1s[64 + k],     fmaf(x2, W1s[128 + k],     b1s[k]))), 0.0f);
            float vb = fmaxf(fmaf(x0, W1s[k + 1], fmaf(x1, W1s[64 + k + 1], fmaf(x2, W1s[128 + k + 1], b1s[k + 1]))), 0.0f);
            uint32_t hh, ll;
            split2(va, vb, hh, ll);
            *(uint32_t*)(sm + K1_A_HI + pl * K1_LDP + k * 2) = hh;
            *(uint32_t*)(sm + K1_A_LO + pl * K1_LDP + k * 2) = ll;
        }
    }
    __syncthreads();

    const uint32_t aRow = (uint32_t)(wm * 32 + (lane & 15));
    const uint32_t aCol = (uint32_t)((lane >> 4) * 16);
    const uint32_t aHi0 = sb + K1_A_HI + aRow * K1_LDP + aCol;
    const uint32_t aHi1 = aHi0 + 16 * K1_LDP;
    const uint32_t aLo0 = sb + K1_A_LO + aRow * K1_LDP + aCol;
    const uint32_t aLo1 = aLo0 + 16 * K1_LDP;
    const uint32_t bRow = (uint32_t)(wn * 32 + (lane & 7) + ((lane >> 4) << 3));
    const uint32_t bCol = (uint32_t)(((lane >> 3) & 1) * 16);
    const uint32_t bHi0 = sb + K1_B_HI + bRow * K1_LDP + bCol;
    const uint32_t bLo0 = sb + K1_B_LO + bRow * K1_LDP + bCol;

    float d[2][4][4];
    #pragma unroll
    for (int mt = 0; mt < 2; ++mt)
        #pragma unroll
        for (int j = 0; j < 4; ++j)
            #pragma unroll
            for (int c = 0; c < 4; ++c) d[mt][j][c] = 0.0f;

    #pragma unroll
    for (int ks = 0; ks < 4; ++ks) {
        const uint32_t ko = ks * 32;
        uint32_t aH0[4], aH1[4], aL0[4], aL1[4];
        LDSM_X4(aH0[0], aH0[1], aH0[2], aH0[3], aHi0 + ko);
        LDSM_X4(aH1[0], aH1[1], aH1[2], aH1[3], aHi1 + ko);
        LDSM_X4(aL0[0], aL0[1], aL0[2], aL0[3], aLo0 + ko);
        LDSM_X4(aL1[0], aL1[1], aL1[2], aL1[3], aLo1 + ko);
        #pragma unroll
        for (int j = 0; j < 2; ++j) {
            uint32_t bH[4], bL[4];
            LDSM_X4(bH[0], bH[1], bH[2], bH[3], bHi0 + j * (16 * K1_LDP) + ko);
            LDSM_X4(bL[0], bL[1], bL[2], bL[3], bLo0 + j * (16 * K1_LDP) + ko);
            mma_f16(d[0][2 * j],     aH0, bH);
            mma_f16(d[1][2 * j],     aH1, bH);
            mma_f16(d[0][2 * j + 1], aH0, bH + 2);
            mma_f16(d[1][2 * j + 1], aH1, bH + 2);
            mma_f16(d[0][2 * j],     aH0, bL);
            mma_f16(d[1][2 * j],     aH1, bL);
            mma_f16(d[0][2 * j + 1], aH0, bL + 2);
            mma_f16(d[1][2 * j + 1], aH1, bL + 2);
            mma_f16(d[0][2 * j],     aL0, bH);
            mma_f16(d[1][2 * j],     aL1, bH);
            mma_f16(d[0][2 * j + 1], aL0, bH + 2);
            mma_f16(d[1][2 * j + 1], aL1, bH + 2);
        }
    }

    // Epilogue: bias+relu in place, hi/lo stores, per-row max, u8 quant
    const int pBase = blockIdx.x * 64;
    float pmax[2][2] = {{0.f, 0.f}, {0.f, 0.f}};
    #pragma unroll
    for (int mt = 0; mt < 2; ++mt) {
        #pragma unroll
        for (int j = 0; j < 4; ++j) {
            const int col = wn * 32 + j * 8 + (lane & 3) * 2;
            const float bc0 = b2s[col], bc1 = b2s[col + 1];
            #pragma unroll
            for (int rr = 0; rr < 2; ++rr) {
                const float v0 = fmaxf(d[mt][j][rr * 2 + 0] + bc0, 0.0f);
                const float v1 = fmaxf(d[mt][j][rr * 2 + 1] + bc1, 0.0f);
                d[mt][j][rr * 2 + 0] = v0;
                d[mt][j][rr * 2 + 1] = v1;
                pmax[mt][rr] = fmaxf(pmax[mt][rr], fmaxf(v0, v1));
                const int row = pBase + wm * 32 + mt * 16 + (lane >> 2) + rr * 8;
                uint32_t hh, ll;
                split2(v0, v1, hh, ll);
                *(uint32_t*)(g_H2hi + (size_t)row * 128 + col) = hh;
                *(uint32_t*)(g_H2lo + (size_t)row * 128 + col) = ll;
            }
        }
    }
    #pragma unroll
    for (int mt = 0; mt < 2; ++mt)
        #pragma unroll
        for (int rr = 0; rr < 2; ++rr) {
            float m = pmax[mt][rr];
            m = fmaxf(m, __shfl_xor_sync(0xffffffffu, m, 1));
            m = fmaxf(m, __shfl_xor_sync(0xffffffffu, m, 2));
            pmax[mt][rr] = m;
        }
    if ((lane & 3) == 0) {
        #pragma unroll
        for (int mt = 0; mt < 2; ++mt)
            #pragma unroll
            for (int rr = 0; rr < 2; ++rr)
                rm[wn * 64 + wm * 32 + mt * 16 + (lane >> 2) + rr * 8] = pmax[mt][rr];
    }
    __syncthreads();
    #pragma unroll
    for (int mt = 0; mt < 2; ++mt) {
        #pragma unroll
        for (int rr = 0; rr < 2; ++rr) {
            const int rl = wm * 32 + mt * 16 + (lane >> 2) + rr * 8;
            const float m = fmaxf(fmaxf(fmaxf(rm[rl], rm[64 + rl]),
                                        fmaxf(rm[128 + rl], rm[192 + rl])), 1e-20f);
            if (wn == 0 && (lane & 3) == 0) g_Sc[pBase + rl] = m * (1.0f / 255.0f);
            const float qs = 255.0f / m;
            #pragma unroll
            for (int j = 0; j < 4; ++j) {
                const int col = wn * 32 + j * 8 + (lane & 3) * 2;
                const int q0 = __float2int_rn(d[mt][j][rr * 2 + 0] * qs);
                const int q1 = __float2int_rn(d[mt][j][rr * 2 + 1] * qs);
                *(uchar2*)(g_H2q + (size_t)(pBase + rl) * 128 + col) =
                    make_uchar2((unsigned char)q0, (unsigned char)q1);
            }
        }
    }
}

// ---------------------------------------------------------------------------
// K2 (persistent, u8xs8, TOP-2 argmax): grid (8 colgroups, 37). Resident
// 128-col int8 B tile (per-column quant, argmax-invariant positive scale).
// Per batch: u8s8 m16n8k32 MMA (half the fp16 instruction count), top-2
// (max,idx) tracked through fold + reductions; fused fixup computes exact
// fp32 dots for BOTH candidates and takes the max.
// ---------------------------------------------------------------------------
#define LDPQ 144
#define AQ_STAGE 9216                 // 64*144
#define OFF_A 0                       // 2 stages u8
#define OFF_SA 18432                  // 2 x 64 floats
#define OFF_B 18944                   // 128*144
#define OFF_CM 37376                  // 128 floats
#define OFF_SV1 37888                 // float[256]
#define OFF_SI1 38912
#define OFF_SV2 39936
#define OFF_SI2 40960
#define K2_SMEM 41984

__global__ void __launch_bounds__(256, 2) k2_persist(const float* __restrict__ W3,
                                                     const float* __restrict__ b3)
{
    char* sm = smem_raw;
    const uint32_t sb = smem_u32(sm);
    const int tid = threadIdx.x, lane = tid & 31, w = tid >> 5;
    const int wm = w & 1, wn = w >> 1;   // 2m x 4n, warp tile 32x32
    const int cg = blockIdx.x;
    const int colBase = cg * 128;
    const int y = blockIdx.y;

    float* sval1 = (float*)(sm + OFF_SV1);
    uint32_t* sidx1 = (uint32_t*)(sm + OFF_SI1);
    float* sval2 = (float*)(sm + OFF_SV2);
    uint32_t* sidx2 = (uint32_t*)(sm + OFF_SI2);
    float* cm = (float*)(sm + OFF_CM);

    // prefetch tile 0 (q + scales) of first batch
    {
        const char* src0 = (const char*)g_H2q + (size_t)y * NPTS * 128;
        const uint32_t dst = sb + OFF_A;
        #pragma unroll
        for (int i = 0; i < 2; ++i) {
            const int idx = tid + i * 256;          // 512 chunks: 64 rows x 8
            const int m = idx >> 3, j = idx & 7;
            CP_ASYNC16(dst + m * LDPQ + j * 16, src0 + idx * 16);
        }
        if (tid < 16)
            CP_ASYNC16(sb + OFF_SA + tid * 16, (const char*)(g_Sc + (size_t)y * NPTS) + tid * 16);
        CP_COMMIT();
    }

    // per-column |max| then int8 B fill (once per CTA)
    if (tid < 128) {
        float m = 0.0f;
        for (int k = 0; k < 128; ++k)
            m = fmaxf(m, fabsf(W3[k * 1024 + colBase + tid]));
        cm[tid] = fmaxf(m, 1e-20f);
    }
    __syncthreads();
    for (int idx = tid; idx < 16384; idx += 256) {
        const int n = idx & 127, k = idx >> 7;
        const int q = __float2int_rn(W3[k * 1024 + colBase + n] * (127.0f / cm[n]));
        *(char*)(sm + OFF_B + n * LDPQ + k) = (char)q;
    }

    const uint32_t aRow = (uint32_t)(wm * 32 + (lane & 15));
    const uint32_t aByte = (uint32_t)((lane >> 4) * 16);
    const uint32_t aOff = aRow * LDPQ + aByte;
    const uint32_t bRow = (uint32_t)(wn * 32 + ((lane >> 4) << 3) + (lane & 7));
    const uint32_t bByte = (uint32_t)(((lane >> 3) & 1) * 16);
    const uint32_t bQ0 = sb + OFF_B + bRow * LDPQ + bByte;

    for (int b = y; b < BATCH; b += 37) {
        const char* srcQ = (const char*)g_H2q + (size_t)b * NPTS * 128;
        const int nb = b + 37;

        float m1[8], m2[8];
        uint32_t i1[8], i2[8];
        #pragma unroll
        for (int i = 0; i < 8; ++i) { m1[i] = -1e30f; m2[i] = -2e30f; i1[i] = 0; i2[i] = 0; }

        for (int t = 0; t < 16; ++t) {
            if (t < 15) {
                const uint32_t dst = sb + OFF_A + ((t + 1) & 1) * AQ_STAGE;
                const int base = (t + 1) * 512;
                #pragma unroll
                for (int i = 0; i < 2; ++i) {
                    const int idx = tid + i * 256;
                    const int m = idx >> 3, j = idx & 7;
                    CP_ASYNC16(dst + m * LDPQ + j * 16, srcQ + (base + idx) * 16);
                }
                if (tid < 16)
                    CP_ASYNC16(sb + OFF_SA + ((t + 1) & 1) * 256 + tid * 16,
                               (const char*)(g_Sc + (size_t)b * NPTS + (t + 1) * 64) + tid * 16);
                CP_COMMIT();
                CP_WAIT(1);
            } else if (nb < BATCH) {
                const char* srcN = (const char*)g_H2q + (size_t)nb * NPTS * 128;
                const uint32_t dst = sb + OFF_A;
                #pragma unroll
                for (int i = 0; i < 2; ++i) {
                    const int idx = tid + i * 256;
                    const int m = idx >> 3, j = idx & 7;
                    CP_ASYNC16(dst + m * LDPQ + j * 16, srcN + idx * 16);
                }
                if (tid < 16)
                    CP_ASYNC16(sb + OFF_SA + tid * 16,
                               (const char*)(g_Sc + (size_t)nb * NPTS) + tid * 16);
                CP_COMMIT();
                CP_WAIT(1);
            } else {
                CP_WAIT(0);
            }
            __syncthreads();

            const uint32_t aQ0 = sb + OFF_A + (t & 1) * AQ_STAGE + aOff;
            const float* saS = (const float*)(sm + OFF_SA + (t & 1) * 256);

            int d[2][4][4];
            #pragma unroll
            for (int mt = 0; mt < 2; ++mt)
                #pragma unroll
                for (int j = 0; j < 4; ++j)
                    #pragma unroll
                    for (int c = 0; c < 4; ++c) d[mt][j][c] = 0;

            #pragma unroll
            for (int ks = 0; ks < 4; ++ks) {           // K=32 per step
                const uint32_t ko = ks * 32;
                uint32_t a0[4], a1[4];
                LDSM_X4(a0[0], a0[1], a0[2], a0[3], aQ0 + ko);
                LDSM_X4(a1[0], a1[1], a1[2], a1[3], aQ0 + 16 * LDPQ + ko);
                #pragma unroll
                for (int j = 0; j < 2; ++j) {
                    uint32_t bq[4];
                    LDSM_X4(bq[0], bq[1], bq[2], bq[3], bQ0 + j * (16 * LDPQ) + ko);
                    mma_u8s8(d[0][2 * j],     a0, bq);
                    mma_u8s8(d[1][2 * j],     a1, bq);
                    mma_u8s8(d[0][2 * j + 1], a0, bq + 2);
                    mma_u8s8(d[1][2 * j + 1], a1, bq + 2);
                }
            }

            // top-2 fold with per-point scale; rows = rbase + {0,8,16,24}
            const int rl = wm * 32 + (lane >> 2);
            const float sa[4] = { saS[rl], saS[rl + 8], saS[rl + 16], saS[rl + 24] };
            const uint32_t rbase = (uint32_t)(t * 64 + rl);
            #pragma unroll
            for (int f = 0; f < 4; ++f) {
                #pragma unroll
                for (int cc = 0; cc < 2; ++cc) {
                    const int e = f * 2 + cc;
                    const float vv[4] = { (float)d[0][f][cc]     * sa[0],
                                          (float)d[0][f][cc + 2] * sa[1],
                                          (float)d[1][f][cc]     * sa[2],
                                          (float)d[1][f][cc + 2] * sa[3] };
                    #pragma unroll
                    for (int r = 0; r < 4; ++r) {
                        const float v = vv[r];
                        const uint32_t vi = rbase + r * 8;
                        if (v > m2[e]) {
                            if (v > m1[e]) { m2[e] = m1[e]; i2[e] = i1[e]; m1[e] = v; i1[e] = vi; }
                            else { m2[e] = v; i2[e] = vi; }
                        }
                    }
                }
            }
            __syncthreads();
        }

        // cross-lane top-2 merge (row lives in lane bits 2..4)
        #pragma unroll
        for (int e = 0; e < 8; ++e) {
            #pragma unroll
            for (int off = 4; off <= 16; off <<= 1) {
                const float o1 = __shfl_xor_sync(0xffffffffu, m1[e], off);
                const uint32_t oi1 = __shfl_xor_sync(0xffffffffu, i1[e], off);
                const float o2 = __shfl_xor_sync(0xffffffffu, m2[e], off);
                const uint32_t oi2 = __shfl_xor_sync(0xffffffffu, i2[e], off);
                if (o1 > m1[e]) {
                    const uint32_t ni2 = (o2 > m1[e]) ? oi2 : i1[e];
                    m2[e] = fmaxf(m1[e], o2);
                    i2[e] = ni2;
                    m1[e] = o1; i1[e] = oi1;
                } else if (o1 > m2[e]) {
                    m2[e] = o1; i2[e] = oi1;
                }
            }
        }
        if (lane < 4) {
            #pragma unroll
            for (int f = 0; f < 4; ++f) {
                #pragma unroll
                for (int cc = 0; cc < 2; ++cc) {
                    const int cl = wn * 32 + f * 8 + lane * 2 + cc;
                    sval1[wm * 128 + cl] = m1[f * 2 + cc];
                    sidx1[wm * 128 + cl] = i1[f * 2 + cc];
                    sval2[wm * 128 + cl] = m2[f * 2 + cc];
                    sidx2[wm * 128 + cl] = i2[f * 2 + cc];
                }
            }
        }
        __syncthreads();

        // Fused exact fixup with top-2 candidates.
        // col = tid&127, k-half = tid>>7 (64 k each)
        {
            const int col = tid & 127;
            const int kh = tid >> 7;
            // merge wm-halves' top-2 -> candidates selA, selB
            const float a1v = sval1[col], a2v = sval2[col];
            const uint32_t ai1 = sidx1[col], ai2 = sidx2[col];
            const float b1v = sval1[128 + col], b2v = sval2[128 + col];
            const uint32_t bi1 = sidx1[128 + col], bi2 = sidx2[128 + col];
            uint32_t selA, selB;
            if (b1v > a1v) {
                selA = bi1;
                selB = (b2v > a1v) ? bi2 : ai1;
            } else {
                selA = ai1;
                selB = (a2v > b1v) ? ai2 : bi1;
            }
            const int gcol = colBase + col;

            const uint4* hiA = (const uint4*)(g_H2hi + ((size_t)b * NPTS + selA) * 128);
            const uint4* loA = (const uint4*)(g_H2lo + ((size_t)b * NPTS + selA) * 128);
            const uint4* hiB = (const uint4*)(g_H2hi + ((size_t)b * NPTS + selB) * 128);
            const uint4* loB = (const uint4*)(g_H2lo + ((size_t)b * NPTS + selB) * 128);

            float accA = 0.0f, accB = 0.0f;
            #pragma unroll
            for (int ci = 0; ci < 8; ++ci) {
                const int c = kh * 8 + ci;
                const uint4 hA = hiA[c], lA = loA[c];
                const uint4 hB = hiB[c], lB = loB[c];
                const uint32_t hwA[4] = {hA.x, hA.y, hA.z, hA.w};
                const uint32_t lwA[4] = {lA.x, lA.y, lA.z, lA.w};
                const uint32_t hwB[4] = {hB.x, hB.y, hB.z, hB.w};
                const uint32_t lwB[4] = {lB.x, lB.y, lB.z, lB.w};
                #pragma unroll
                for (int q = 0; q < 4; ++q) {
                    const int k = c * 8 + q * 2;
                    const float w0 = W3[(size_t)k * 1024 + gcol];
                    const float w1 = W3[(size_t)(k + 1) * 1024 + gcol];
                    {
                        const __half2 hh = *(const __half2*)&hwA[q];
                        const __half2 ll = *(const __half2*)&lwA[q];
                        const float a0 = __half2float(__low2half(hh))  + __half2float(__low2half(ll));
                        const float a1 = __half2float(__high2half(hh)) + __half2float(__high2half(ll));
                        accA = fmaf(a0, w0, accA);
                        accA = fmaf(a1, w1, accA);
                    }
                    {
                        const __half2 hh = *(const __half2*)&hwB[q];
                        const __half2 ll = *(const __half2*)&lwB[q];
                        const float a0 = __half2float(__low2half(hh))  + __half2float(__low2half(ll));
                        const float a1 = __half2float(__high2half(hh)) + __half2float(__high2half(ll));
                        accB = fmaf(a0, w0, accB);
                        accB = fmaf(a1, w1, accB);
                    }
                }
            }
            __syncthreads();                 // sval/sidx fully consumed
            sval1[tid] = accA;               // tid == kh*128 + col
            sval2[tid] = accB;
            __syncthreads();
            if (tid < 128) {
                const float dA = sval1[tid] + sval1[128 + tid];
                const float dB = sval2[tid] + sval2[128 + tid];
                g_G[b * 1024 + colBase + tid] =
                    fmaxf(fmaxf(dA, dB) + b3[colBase + tid], 0.0f);
            }
        }
        __syncthreads();
    }
}

// ---------------------------------------------------------------------------
// Head GEMMs: 16x64 tile, split-K x2 (512 threads), 3-stage cp.async per half.
// ---------------------------------------------------------------------------
#define HD2_AS 1088
#define HD2_BS 4096
#define HD2_STAGE (HD2_AS + HD2_BS)
#define HD2_SMEM (6 * HD2_STAGE * 4)

__device__ __forceinline__ void hd2_load_chunk(
    uint32_t as, uint32_t bs,
    const float* __restrict__ A, const float* __restrict__ B,
    int rowBase, int colBase, int K, int ldb, int k0, int t256)
{
    {
        const int r = t256 >> 4, k = (t256 & 15) * 4;
        CP_ASYNC16(as + (r * 68 + k) * 4, A + (size_t)(rowBase + r) * K + k0 + k);
    }
    #pragma unroll
    for (int i = 0; i < 4; ++i) {
        const int idx = t256 + i * 256;
        const int r = idx >> 4, c = (idx & 15) * 4;
        CP_ASYNC16(bs + (r * 64 + c) * 4, B + (size_t)(k0 + r) * ldb + colBase + c);
    }
}

__device__ __forceinline__ void head_gemm_splitk(
    const float* __restrict__ A, const float* __restrict__ B,
    const float* __restrict__ bias, float* __restrict__ C,
    int K, int ldb, bool relu)
{
    float* sm = (float*)smem_raw;
    const uint32_t sb = smem_u32(sm);
    const int tid = threadIdx.x;
    const int kh = tid >> 8;
    const int t256 = tid & 255;
    const int tx = t256 & 15, ty = t256 >> 4;
    const int rowBase = blockIdx.x * 16;
    const int colBase = blockIdx.y * 64;
    const int nCh = K >> 7;
    const int kBase = kh * (K >> 1);

    const uint32_t st[3] = { sb + (uint32_t)(kh * 3 + 0) * HD2_STAGE * 4,
                             sb + (uint32_t)(kh * 3 + 1) * HD2_STAGE * 4,
                             sb + (uint32_t)(kh * 3 + 2) * HD2_STAGE * 4 };

    hd2_load_chunk(st[0], st[0] + HD2_AS * 4, A, B, rowBase, colBase, K, ldb, kBase, t256);
    CP_COMMIT();
    if (nCh > 1) {
        hd2_load_chunk(st[1], st[1] + HD2_AS * 4, A, B, rowBase, colBase, K, ldb, kBase + 64, t256);
        CP_COMMIT();
    }

    float acc[4] = {0.0f, 0.0f, 0.0f, 0.0f};

    for (int ch = 0; ch < nCh; ++ch) {
        if (ch + 2 < nCh) {
            const uint32_t as = st[(ch + 2) % 3];
            hd2_load_chunk(as, as + HD2_AS * 4, A, B, rowBase, colBase, K, ldb,
                           kBase + (ch + 2) * 64, t256);
            CP_COMMIT();
            CP_WAIT(2);
        } else if (ch + 1 < nCh) {
            CP_WAIT(1);
        } else {
            CP_WAIT(0);
        }
        __syncthreads();

        const float* AsF = sm + ((kh * 3 + (ch % 3)) * HD2_STAGE);
        const float* BsF = AsF + HD2_AS;

        #pragma unroll 16
        for (int k = 0; k < 64; ++k) {
            const float4 wv = *(const float4*)(BsF + k * 64 + tx * 4);
            const float a0 = AsF[ty * 68 + k];
            acc[0] = fmaf(a0, wv.x, acc[0]); acc[1] = fmaf(a0, wv.y, acc[1]);
            acc[2] = fmaf(a0, wv.z, acc[2]); acc[3] = fmaf(a0, wv.w, acc[3]);
        }
        __syncthreads();
    }

    float* red = sm;
    if (kh == 1) {
        *(float4*)(red + t256 * 4) = make_float4(acc[0], acc[1], acc[2], acc[3]);
    }
    __syncthreads();
    if (kh == 0) {
        const float4 o = *(const float4*)(red + t256 * 4);
        const float s[4] = {acc[0] + o.x, acc[1] + o.y, acc[2] + o.z, acc[3] + o.w};
        #pragma unroll
        for (int c = 0; c < 4; ++c) {
            float v = s[c] + bias[colBase + tx * 4 + c];
            if (relu) v = fmaxf(v, 0.0f);
            C[(size_t)(rowBase + ty) * ldb + colBase + tx * 4 + c] = v;
        }
    }
}

__global__ void __launch_bounds__(512, 1) k3_head1(const float* __restrict__ Wh1, const float* __restrict__ bh1) {
    head_gemm_splitk(g_G, Wh1, bh1, g_Z1, 1024, 512, true);
}
__global__ void __launch_bounds__(512, 1) k4_head2(const float* __restrict__ Wh2, const float* __restrict__ bh2) {
    head_gemm_splitk(g_Z1, Wh2, bh2, g_Z2, 512, 256, true);
}

// ---------------------------------------------------------------------------
// K5: raw = Z2 @ Wh3 + bh3 — warp per output, shfl reduce.
// ---------------------------------------------------------------------------
__global__ void k5_raw(const float* __restrict__ Wh3, const float* __restrict__ bh3)
{
    const int g = blockIdx.x * 8 + (threadIdx.x >> 5);
    if (g >= BATCH * 9) return;
    const int lane = threadIdx.x & 31;
    const int b = g / 9, j = g % 9;
    const float* z = g_Z2 + b * 256;
    float acc = 0.0f;
    #pragma unroll
    for (int i = 0; i < 8; ++i) {
        const int k = lane + i * 32;
        acc = fmaf(z[k], Wh3[k * 9 + j], acc);
    }
    #pragma unroll
    for (int off = 16; off > 0; off >>= 1)
        acc += __shfl_xor_sync(0xffffffffu, acc, off);
    if (lane == 0) g_RAW[g] = acc + bh3[j];
}

// ---------------------------------------------------------------------------
// K6: SVD projection onto SO(3). One thread per 3x3 matrix.
// ---------------------------------------------------------------------------
__device__ __forceinline__ void jrot(float A[3][3], float V[3][3], int p, int q)
{
    float apq = A[p][q];
    if (fabsf(apq) < 1e-20f) return;
    float tau = (A[q][q] - A[p][p]) / (2.0f * apq);
    float t = copysignf(1.0f, tau) / (fabsf(tau) + sqrtf(1.0f + tau * tau));
    float c = 1.0f / sqrtf(1.0f + t * t);
    float s = t * c;
    for (int r = 0; r < 3; ++r) {
        float arp = A[r][p], arq = A[r][q];
        A[r][p] = c * arp - s * arq;
        A[r][q] = s * arp + c * arq;
    }
    for (int r = 0; r < 3; ++r) {
        float apr = A[p][r], aqr = A[q][r];
        A[p][r] = c * apr - s * aqr;
        A[q][r] = s * apr + c * aqr;
    }
    for (int r = 0; r < 3; ++r) {
        float vrp = V[r][p], vrq = V[r][q];
        V[r][p] = c * vrp - s * vrq;
        V[r][q] = s * vrp + c * vrq;
    }
}

__global__ void k6_svd(float* __restrict__ out)
{
    int i = blockIdx.x * 32 + threadIdx.x;
    if (i >= BATCH) return;

    float M[3][3];
    for (int r = 0; r < 3; ++r)
        for (int c = 0; c < 3; ++c)
            M[r][c] = g_RAW[i * 9 + r * 3 + c];

    float A[3][3], V[3][3];
    for (int r = 0; r < 3; ++r)
        for (int c = 0; c < 3; ++c) {
            A[r][c] = M[0][r] * M[0][c] + M[1][r] * M[1][c] + M[2][r] * M[2][c];
            V[r][c] = (r == c) ? 1.0f : 0.0f;
        }

    for (int sweep = 0; sweep < 12; ++sweep) {
        jrot(A, V, 0, 1);
        jrot(A, V, 0, 2);
        jrot(A, V, 1, 2);
    }

    float e0 = A[0][0], e1 = A[1][1], e2 = A[2][2];
    int i0 = 0, i1 = 1, i2 = 2;
    if (e0 < e1) { float t = e0; e0 = e1; e1 = t; int ti = i0; i0 = i1; i1 = ti; }
    if (e0 < e2) { float t = e0; e0 = e2; e2 = t; int ti = i0; i0 = i2; i2 = ti; }
    if (e1 < e2) { float t = e1; e1 = e2; e2 = t; int ti = i1; i1 = i2; i2 = ti; }

    float v1[3], v2[3], v3[3];
    for (int r = 0; r < 3; ++r) { v1[r] = V[r][i0]; v2[r] = V[r][i1]; v3[r] = V[r][i2]; }

    float detV = v1[0] * (v2[1] * v3[2] - v2[2] * v3[1])
               - v1[1] * (v2[0] * v3[2] - v2[2] * v3[0])
               + v1[2] * (v2[0] * v3[1] - v2[1] * v3[0]);

    float w1[3], w2[3];
    for (int r = 0; r < 3; ++r) {
        w1[r] = M[r][0] * v1[0] + M[r][1] * v1[1] + M[r][2] * v1[2];
        w2[r] = M[r][0] * v2[0] + M[r][1] * v2[1] + M[r][2] * v2[2];
    }
    float n1 = sqrtf(w1[0] * w1[0] + w1[1] * w1[1] + w1[2] * w1[2] + 1e-30f);
    float u1[3] = { w1[0] / n1, w1[1] / n1, w1[2] / n1 };
    float d12 = u1[0] * w2[0] + u1[1] * w2[1] + u1[2] * w2[2];
    for (int r = 0; r < 3; ++r) w2[r] -= d12 * u1[r];
    float n2 = sqrtf(w2[0] * w2[0] + w2[1] * w2[1] + w2[2] * w2[2] + 1e-30f);
    float u2[3] = { w2[0] / n2, w2[1] / n2, w2[2] / n2 };
    float u3[3] = { u1[1] * u2[2] - u1[2] * u2[1],
                    u1[2] * u2[0] - u1[0] * u2[2],
                    u1[0] * u2[1] - u1[1] * u2[0] };
    if (detV < 0.0f) { u3[0] = -u3[0]; u3[1] = -u3[1]; u3[2] = -u3[2]; }

    for (int r = 0; r < 3; ++r)
        for (int c = 0; c < 3; ++c)
            out[i * 9 + r * 3 + c] = u1[r] * v1[c] + u2[r] * v2[c] + u3[r] * v3[c];
}

// ---------------------------------------------------------------------------
extern "C" void kernel_launch(void* const* d_in, const int* in_sizes, int n_in,
                              void* d_out, int out_size)
{
    const float* x   = (const float*)d_in[0];
    const float* W1  = (const float*)d_in[1];
    const float* b1  = (const float*)d_in[2];
    const float* W2  = (const float*)d_in[3];
    const float* b2  = (const float*)d_in[4];
    const float* W3  = (const float*)d_in[5];
    const float* b3  = (const float*)d_in[6];
    const float* Wh1 = (const float*)d_in[7];
    const float* bh1 = (const float*)d_in[8];
    const float* Wh2 = (const float*)d_in[9];
    const float* bh2 = (const float*)d_in[10];
    const float* Wh3 = (const float*)d_in[11];
    const float* bh3 = (const float*)d_in[12];
    float* out = (float*)d_out;

    cudaFuncSetAttribute(k1_point_mlp, cudaFuncAttributeMaxDynamicSharedMemorySize, K1_SMEM);
    cudaFuncSetAttribute(k2_persist,   cudaFuncAttributeMaxDynamicSharedMemorySize, K2_SMEM);
    cudaFuncSetAttribute(k3_head1,     cudaFuncAttributeMaxDynamicSharedMemorySize, HD2_SMEM);
    cudaFuncSetAttribute(k4_head2,     cudaFuncAttributeMaxDynamicSharedMemorySize, HD2_SMEM);

    k1_point_mlp<<<4096, 256, K1_SMEM>>>(x, W1, b1, W2, b2);
    k2_persist<<<dim3(8, 37), 256, K2_SMEM>>>(W3, b3);
    k3_head1<<<dim3(16, 8), 512, HD2_SMEM>>>(Wh1, bh1);
    k4_head2<<<dim3(16, 4), 512, HD2_SMEM>>>(Wh2, bh2);
    k5_raw<<<288, 256>>>(Wh3, bh3);
    k6_svd<<<8, 32>>>(out);

    (void)in_sizes; (void)n_in; (void)out_size;
}

// round 16
// speedup vs baseline: 2.0298x; 2.0298x over previous
#include <cuda_runtime.h>
#include <cuda_fp16.h>
#include <math.h>
#include <cstdint>

#define BATCH 256
#define NPTS  1024

// Scratch (device globals — allocation-free contract)
__device__ __half g_H2hi[BATCH * NPTS * 128];   // 64 MB
__device__ __half g_H2lo[BATCH * NPTS * 128];   // 64 MB
__device__ unsigned g_AMAX[BATCH * 1024];
__device__ float g_G[BATCH * 1024];
__device__ float g_Z1[BATCH * 512];
__device__ float g_Z2[BATCH * 256];
__device__ float g_RAW[BATCH * 9];

extern __shared__ char smem_raw[];

__device__ __forceinline__ uint32_t smem_u32(const void* p) {
    uint32_t a;
    asm("{ .reg .u64 t; cvta.to.shared.u64 t, %1; cvt.u32.u64 %0, t; }" : "=r"(a) : "l"(p));
    return a;
}

#define LDSM_X4(r0, r1, r2, r3, addr) \
    asm volatile("ldmatrix.sync.aligned.m8n8.x4.shared.b16 {%0,%1,%2,%3}, [%4];" \
                 : "=r"(r0), "=r"(r1), "=r"(r2), "=r"(r3) : "r"(addr))

__device__ __forceinline__ void mma_f16(float* d, const uint32_t* a, const uint32_t* b) {
    asm volatile("mma.sync.aligned.m16n8k16.row.col.f32.f16.f16.f32 "
                 "{%0,%1,%2,%3},{%4,%5,%6,%7},{%8,%9},{%0,%1,%2,%3};"
                 : "+f"(d[0]), "+f"(d[1]), "+f"(d[2]), "+f"(d[3])
                 : "r"(a[0]), "r"(a[1]), "r"(a[2]), "r"(a[3]), "r"(b[0]), "r"(b[1]));
}

// fp16-accumulate variant: D,C are 2 x .f16x2 regs (row r in d[0], row r+8 in d[1])
__device__ __forceinline__ void mma_f16acc(uint32_t* d, const uint32_t* a, const uint32_t* b) {
    asm volatile("mma.sync.aligned.m16n8k16.row.col.f16.f16.f16.f16 "
                 "{%0,%1},{%2,%3,%4,%5},{%6,%7},{%0,%1};"
                 : "+r"(d[0]), "+r"(d[1])
                 : "r"(a[0]), "r"(a[1]), "r"(a[2]), "r"(a[3]), "r"(b[0]), "r"(b[1]));
}

__device__ __forceinline__ uint32_t h2u(__half2 v) {
    uint32_t u; *(__half2*)&u = v; return u;
}

__device__ __forceinline__ void split2(float va, float vb, uint32_t& hi, uint32_t& lo) {
    __half2 h = __floats2half2_rn(va, vb);
    __half2 l = __floats2half2_rn(va - __half2float(__low2half(h)),
                                  vb - __half2float(__high2half(h)));
    hi = h2u(h); lo = h2u(l);
}

#define CP_ASYNC16(dst, src) \
    asm volatile("cp.async.cg.shared.global [%0], [%1], 16;" :: "r"(dst), "l"(src))
#define CP_COMMIT() asm volatile("cp.async.commit_group;" ::: "memory")
#define CP_WAIT(n)  asm volatile("cp.async.wait_group %0;" :: "n"(n) : "memory")

// ---------------------------------------------------------------------------
// K1: per-point MLP 3 -> 64 (scalar) -> 128 (HMMA fp16 3-combo hi/lo, fp32 acc),
// fused bias+ReLU+split epilogue, writes g_H2hi/g_H2lo.
// ---------------------------------------------------------------------------
#define K1_LDP 144
#define K1_A_HI 0
#define K1_A_LO 18432
#define K1_B_HI 36864
#define K1_B_LO 55296
#define K1_W1S  73728
#define K1_B1S  74496
#define K1_B2S  74752
#define K1_SMEM 75264

__global__ void __launch_bounds__(512, 1) k1_point_mlp(
    const float* __restrict__ x,
    const float* __restrict__ W1, const float* __restrict__ b1,
    const float* __restrict__ W2, const float* __restrict__ b2)
{
    char* sm = smem_raw;
    const uint32_t sb = smem_u32(sm);
    const int tid = threadIdx.x, lane = tid & 31, w = tid >> 5;
    const int wm = w & 3, wn = w >> 2;
    float* W1s = (float*)(sm + K1_W1S);
    float* b1s = (float*)(sm + K1_B1S);
    float* b2s = (float*)(sm + K1_B2S);

    for (int i = tid; i < 8192; i += 512) {
        const int n = i & 127, k = i >> 7;
        const float v = W2[k * 128 + n];
        const __half h = __float2half_rn(v);
        const __half l = __float2half_rn(v - __half2float(h));
        *(__half*)(sm + K1_B_HI + n * K1_LDP + k * 2) = h;
        *(__half*)(sm + K1_B_LO + n * K1_LDP + k * 2) = l;
    }
    if (tid < 192) W1s[tid] = W1[tid];
    else if (tid >= 256 && tid < 320) b1s[tid - 256] = b1[tid - 256];
    else if (tid >= 384 && tid < 512) b2s[tid - 384] = b2[tid - 384];
    __syncthreads();

    {
        const int pl = tid & 127;
        const int ks = (tid >> 7) * 16;
        const int pg = blockIdx.x * 128 + pl;
        const float x0 = x[pg * 3 + 0];
        const float x1 = x[pg * 3 + 1];
        const float x2 = x[pg * 3 + 2];
        #pragma unroll
        for (int kk = 0; kk < 16; kk += 2) {
            const int k = ks + kk;
            float va = fmaxf(fmaf(x0, W1s[k],     fmaf(x1, W1s[64 + k],     fmaf(x2, W1s[128 + k],     b1s[k]))), 0.0f);
            float vb = fmaxf(fmaf(x0, W1s[k + 1], fmaf(x1, W1s[64 + k + 1], fmaf(x2, W1s[128 + k + 1], b1s[k + 1]))), 0.0f);
            uint32_t hh, ll;
            split2(va, vb, hh, ll);
            *(uint32_t*)(sm + K1_A_HI + pl * K1_LDP + k * 2) = hh;
            *(uint32_t*)(sm + K1_A_LO + pl * K1_LDP + k * 2) = ll;
        }
    }
    __syncthreads();

    const uint32_t aRow = (uint32_t)(wm * 32 + (lane & 15));
    const uint32_t aCol = (uint32_t)((lane >> 4) * 16);
    const uint32_t aHi0 = sb + K1_A_HI + aRow * K1_LDP + aCol;
    const uint32_t aHi1 = aHi0 + 16 * K1_LDP;
    const uint32_t aLo0 = sb + K1_A_LO + aRow * K1_LDP + aCol;
    const uint32_t aLo1 = aLo0 + 16 * K1_LDP;
    const uint32_t bRow = (uint32_t)(wn * 32 + (lane & 7) + ((lane >> 4) << 3));
    const uint32_t bCol = (uint32_t)(((lane >> 3) & 1) * 16);
    const uint32_t bHi0 = sb + K1_B_HI + bRow * K1_LDP + bCol;
    const uint32_t bLo0 = sb + K1_B_LO + bRow * K1_LDP + bCol;

    float d[2][4][4];
    #pragma unroll
    for (int mt = 0; mt < 2; ++mt)
        #pragma unroll
        for (int j = 0; j < 4; ++j)
            #pragma unroll
            for (int c = 0; c < 4; ++c) d[mt][j][c] = 0.0f;

    #pragma unroll
    for (int ks = 0; ks < 4; ++ks) {
        const uint32_t ko = ks * 32;
        uint32_t aH0[4], aH1[4], aL0[4], aL1[4];
        LDSM_X4(aH0[0], aH0[1], aH0[2], aH0[3], aHi0 + ko);
        LDSM_X4(aH1[0], aH1[1], aH1[2], aH1[3], aHi1 + ko);
        LDSM_X4(aL0[0], aL0[1], aL0[2], aL0[3], aLo0 + ko);
        LDSM_X4(aL1[0], aL1[1], aL1[2], aL1[3], aLo1 + ko);
        #pragma unroll
        for (int j = 0; j < 2; ++j) {
            uint32_t bH[4], bL[4];
            LDSM_X4(bH[0], bH[1], bH[2], bH[3], bHi0 + j * (16 * K1_LDP) + ko);
            LDSM_X4(bL[0], bL[1], bL[2], bL[3], bLo0 + j * (16 * K1_LDP) + ko);
            mma_f16(d[0][2 * j],     aH0, bH);
            mma_f16(d[1][2 * j],     aH1, bH);
            mma_f16(d[0][2 * j + 1], aH0, bH + 2);
            mma_f16(d[1][2 * j + 1], aH1, bH + 2);
            mma_f16(d[0][2 * j],     aH0, bL);
            mma_f16(d[1][2 * j],     aH1, bL);
            mma_f16(d[0][2 * j + 1], aH0, bL + 2);
            mma_f16(d[1][2 * j + 1], aH1, bL + 2);
            mma_f16(d[0][2 * j],     aL0, bH);
            mma_f16(d[1][2 * j],     aL1, bH);
            mma_f16(d[0][2 * j + 1], aL0, bH + 2);
            mma_f16(d[1][2 * j + 1], aL1, bH + 2);
        }
    }

    const int pBase = blockIdx.x * 128;
    #pragma unroll
    for (int mt = 0; mt < 2; ++mt) {
        #pragma unroll
        for (int j = 0; j < 4; ++j) {
            const int col = wn * 32 + j * 8 + (lane & 3) * 2;
            const float bc0 = b2s[col], bc1 = b2s[col + 1];
            #pragma unroll
            for (int rr = 0; rr < 2; ++rr) {
                const int row = pBase + wm * 32 + mt * 16 + (lane >> 2) + rr * 8;
                const float v0 = fmaxf(d[mt][j][rr * 2 + 0] + bc0, 0.0f);
                const float v1 = fmaxf(d[mt][j][rr * 2 + 1] + bc1, 0.0f);
                uint32_t hh, ll;
                split2(v0, v1, hh, ll);
                *(uint32_t*)(g_H2hi + (size_t)row * 128 + col) = hh;
                *(uint32_t*)(g_H2lo + (size_t)row * 128 + col) = ll;
            }
        }
    }
}

// ---------------------------------------------------------------------------
// K2a: 1-combo fp16 HMMA (fp16 accumulate) + argmax-pool. Writes g_AMAX.
// 256 threads = 8 warps (2m x 4n), warp tile 32x64, cp.async double-buffered.
// ---------------------------------------------------------------------------
#define LDP 272
#define A_STAGE 17408                 // 64*272
#define OFF_A 0                       // 2 stages (hi only)
#define OFF_B 34816                   // 256*272
#define OFF_SV 104448                 // float[512]
#define OFF_SI 106496                 // uint[512]
#define K2_SMEM 108544

__global__ void __launch_bounds__(256, 2) k2_gemm_amax(const float* __restrict__ W3)
{
    char* sm = smem_raw;
    const uint32_t sb = smem_u32(sm);
    const int tid = threadIdx.x, lane = tid & 31, w = tid >> 5;
    const int wm = w & 1, wn = w >> 1;          // 2m x 4n
    const int b = blockIdx.y;
    const int colBase = blockIdx.x * 256;

    float* sval = (float*)(sm + OFF_SV);
    uint32_t* sidx = (uint32_t*)(sm + OFF_SI);

    const __half* srcHi = g_H2hi + (size_t)b * NPTS * 128;

    // tile 0 A-hi prefetch (overlaps B conversion fill)
    {
        const uint32_t dst = sb + OFF_A;
        #pragma unroll
        for (int i = 0; i < 4; ++i) {
            const int idx = tid + i * 256;
            const int m = idx >> 4, j = idx & 15;
            CP_ASYNC16(dst + m * LDP + j * 16, (const char*)srcHi + idx * 16);
        }
        CP_COMMIT();
    }

    // B fill: Bs[n][k] = fp16(W3[k][colBase+n]) (hi only)
    for (int idx = tid; idx < 32768; idx += 256) {
        const int n = idx & 255, k = idx >> 8;
        *(__half*)(sm + OFF_B + n * LDP + k * 2) = __float2half_rn(W3[k * 1024 + colBase + n]);
    }

    const uint32_t aRow = (uint32_t)(wm * 32 + (lane & 15));
    const uint32_t aCol = (uint32_t)((lane >> 4) * 16);
    const uint32_t aOff = aRow * LDP + aCol;
    const uint32_t bRow = (uint32_t)(wn * 64 + (lane & 7) + ((lane >> 4) << 3));
    const uint32_t bColB = (uint32_t)(((lane >> 3) & 1) * 16);
    const uint32_t bH0 = sb + OFF_B + bRow * LDP + bColB;

    float runmax[16];
    uint32_t runidx[16];
    #pragma unroll
    for (int i = 0; i < 16; ++i) { runmax[i] = -1e30f; runidx[i] = 0; }

    for (int t = 0; t < 16; ++t) {
        if (t < 15) {
            const uint32_t dst = sb + OFF_A + ((t + 1) & 1) * A_STAGE;
            const int base = (t + 1) * 1024;
            #pragma unroll
            for (int i = 0; i < 4; ++i) {
                const int idx = tid + i * 256;
                const int m = idx >> 4, j = idx & 15;
                CP_ASYNC16(dst + m * LDP + j * 16, (const char*)srcHi + (base + idx) * 16);
            }
            CP_COMMIT();
            CP_WAIT(1);
        } else {
            CP_WAIT(0);
        }
        __syncthreads();

        const uint32_t aHi0 = sb + OFF_A + (t & 1) * A_STAGE + aOff;

        uint32_t dd[2][8][2];     // fp16x2 accumulators: [mt][ntile][row r / r+8]
        #pragma unroll
        for (int mt = 0; mt < 2; ++mt)
            #pragma unroll
            for (int j = 0; j < 8; ++j) { dd[mt][j][0] = 0u; dd[mt][j][1] = 0u; }

        #pragma unroll
        for (int ks = 0; ks < 8; ++ks) {
            const uint32_t ko = ks * 32;
            uint32_t aH0[4], aH1[4];
            LDSM_X4(aH0[0], aH0[1], aH0[2], aH0[3], aHi0 + ko);
            LDSM_X4(aH1[0], aH1[1], aH1[2], aH1[3], aHi0 + 16 * LDP + ko);
            #pragma unroll
            for (int j = 0; j < 4; ++j) {
                uint32_t bH[4];
                LDSM_X4(bH[0], bH[1], bH[2], bH[3], bH0 + j * (16 * LDP) + ko);
                mma_f16acc(dd[0][2 * j],     aH0, bH);
                mma_f16acc(dd[1][2 * j],     aH1, bH);
                mma_f16acc(dd[0][2 * j + 1], aH0, bH + 2);
                mma_f16acc(dd[1][2 * j + 1], aH1, bH + 2);
            }
        }

        // fold (max, argmax): candidate rows = rbase + {0,8,16,24}
        const uint32_t rbase = (uint32_t)(t * 64 + wm * 32 + (lane >> 2));
        #pragma unroll
        for (int f = 0; f < 8; ++f) {
            const float2 rA = __half22float2(*(const __half2*)&dd[0][f][0]); // row r
            const float2 rB = __half22float2(*(const __half2*)&dd[0][f][1]); // row r+8
            const float2 rC = __half22float2(*(const __half2*)&dd[1][f][0]); // row r+16
            const float2 rD = __half22float2(*(const __half2*)&dd[1][f][1]); // row r+24
            #pragma unroll
            for (int cc = 0; cc < 2; ++cc) {
                const int e = f * 2 + cc;
                const float v0 = cc ? rA.y : rA.x;
                const float v1 = cc ? rB.y : rB.x;
                const float v2 = cc ? rC.y : rC.x;
                const float v3 = cc ? rD.y : rD.x;
                if (v0 > runmax[e]) { runmax[e] = v0; runidx[e] = rbase; }
                if (v1 > runmax[e]) { runmax[e] = v1; runidx[e] = rbase + 8; }
                if (v2 > runmax[e]) { runmax[e] = v2; runidx[e] = rbase + 16; }
                if (v3 > runmax[e]) { runmax[e] = v3; runidx[e] = rbase + 24; }
            }
        }
        __syncthreads();
    }

    // cross-lane (row lives in lane bits 2..4): reduce val+idx
    #pragma unroll
    for (int e = 0; e < 16; ++e) {
        #pragma unroll
        for (int off = 4; off <= 16; off <<= 1) {
            const float ov = __shfl_xor_sync(0xffffffffu, runmax[e], off);
            const uint32_t oi = __shfl_xor_sync(0xffffffffu, runidx[e], off);
            if (ov > runmax[e]) { runmax[e] = ov; runidx[e] = oi; }
        }
    }
    if (lane < 4) {
        #pragma unroll
        for (int f = 0; f < 8; ++f) {
            #pragma unroll
            for (int cc = 0; cc < 2; ++cc) {
                const int cl = wn * 64 + f * 8 + lane * 2 + cc;
                sval[wm * 256 + cl] = runmax[f * 2 + cc];
                sidx[wm * 256 + cl] = runidx[f * 2 + cc];
            }
        }
    }
    __syncthreads();
    {
        const float v0 = sval[tid], v1 = sval[256 + tid];
        g_AMAX[b * 1024 + colBase + tid] = (v1 > v0) ? sidx[256 + tid] : sidx[tid];
    }
}

// ---------------------------------------------------------------------------
// K2b: exact fixup. g[b][col] = relu(fp32 dot(h2[argmax], W3[:,col]) + b3).
// ---------------------------------------------------------------------------
__global__ void __launch_bounds__(256) k2_fixup(const float* __restrict__ W3,
                                                const float* __restrict__ b3)
{
    const int tid = threadIdx.x;
    const int b = blockIdx.y;
    const int col = blockIdx.x * 256 + tid;
    const unsigned i = g_AMAX[b * 1024 + col];

    const uint4* hi = (const uint4*)(g_H2hi + ((size_t)b * NPTS + i) * 128);
    const uint4* lo = (const uint4*)(g_H2lo + ((size_t)b * NPTS + i) * 128);

    float acc = 0.0f;
    #pragma unroll
    for (int c = 0; c < 16; ++c) {
        const uint4 h4 = hi[c];
        const uint4 l4 = lo[c];
        const uint32_t hw[4] = {h4.x, h4.y, h4.z, h4.w};
        const uint32_t lw[4] = {l4.x, l4.y, l4.z, l4.w};
        #pragma unroll
        for (int q = 0; q < 4; ++q) {
            const __half2 hh = *(const __half2*)&hw[q];
            const __half2 ll = *(const __half2*)&lw[q];
            const int k = c * 8 + q * 2;
            const float a0 = __half2float(__low2half(hh))  + __half2float(__low2half(ll));
            const float a1 = __half2float(__high2half(hh)) + __half2float(__high2half(ll));
            acc = fmaf(a0, W3[(size_t)k * 1024 + col], acc);
            acc = fmaf(a1, W3[(size_t)(k + 1) * 1024 + col], acc);
        }
    }
    g_G[b * 1024 + col] = fmaxf(acc + b3[col], 0.0f);
}

// ---------------------------------------------------------------------------
// Head GEMMs: 16x64 tile, split-K x2 (512 threads), 2-stage cp.async per half.
// ---------------------------------------------------------------------------
#define HD2_AS 1088    // 16*68 floats
#define HD2_BS 4096    // 64*64 floats
#define HD2_STAGE (HD2_AS + HD2_BS)
#define HD2_SMEM (4 * HD2_STAGE * 4)   // 2 halves x 2 stages

__device__ __forceinline__ void hd2_load_chunk(
    uint32_t as, uint32_t bs,
    const float* __restrict__ A, const float* __restrict__ B,
    int rowBase, int colBase, int K, int ldb, int k0, int t256)
{
    {
        const int r = t256 >> 4, k = (t256 & 15) * 4;
        CP_ASYNC16(as + (r * 68 + k) * 4, A + (size_t)(rowBase + r) * K + k0 + k);
    }
    #pragma unroll
    for (int i = 0; i < 4; ++i) {
        const int idx = t256 + i * 256;
        const int r = idx >> 4, c = (idx & 15) * 4;
        CP_ASYNC16(bs + (r * 64 + c) * 4, B + (size_t)(k0 + r) * ldb + colBase + c);
    }
}

__device__ __forceinline__ void head_gemm_splitk(
    const float* __restrict__ A, const float* __restrict__ B,
    const float* __restrict__ bias, float* __restrict__ C,
    int K, int ldb, bool relu)
{
    float* sm = (float*)smem_raw;
    const uint32_t sb = smem_u32(sm);
    const int tid = threadIdx.x;
    const int kh = tid >> 8;            // k-half 0/1
    const int t256 = tid & 255;
    const int tx = t256 & 15, ty = t256 >> 4;
    const int rowBase = blockIdx.x * 16;
    const int colBase = blockIdx.y * 64;
    const int nCh = K >> 7;             // chunks of 64 per half
    const int kBase = kh * (K >> 1);
    const uint32_t stage0 = sb + (2 * kh) * HD2_STAGE * 4;
    const uint32_t stage1 = sb + (2 * kh + 1) * HD2_STAGE * 4;

    hd2_load_chunk(stage0, stage0 + HD2_AS * 4, A, B, rowBase, colBase, K, ldb, kBase, t256);
    CP_COMMIT();

    float acc[4] = {0.0f, 0.0f, 0.0f, 0.0f};

    for (int ch = 0; ch < nCh; ++ch) {
        if (ch + 1 < nCh) {
            const uint32_t as = (ch + 1) & 1 ? stage1 : stage0;
            hd2_load_chunk(as, as + HD2_AS * 4, A, B, rowBase, colBase, K, ldb,
                           kBase + (ch + 1) * 64, t256);
            CP_COMMIT();
            CP_WAIT(1);
        } else {
            CP_WAIT(0);
        }
        __syncthreads();

        const float* As = sm + ((2 * kh + (ch & 1)) * HD2_STAGE);
        const float* Bs = As + HD2_AS;

        #pragma unroll 16
        for (int k = 0; k < 64; ++k) {
            const float4 wv = *(const float4*)(Bs + k * 64 + tx * 4);
            const float a0 = As[ty * 68 + k];
            acc[0] = fmaf(a0, wv.x, acc[0]); acc[1] = fmaf(a0, wv.y, acc[1]);
            acc[2] = fmaf(a0, wv.z, acc[2]); acc[3] = fmaf(a0, wv.w, acc[3]);
        }
        __syncthreads();
    }

    float* red = sm;
    if (kh == 1) {
        *(float4*)(red + t256 * 4) = make_float4(acc[0], acc[1], acc[2], acc[3]);
    }
    __syncthreads();
    if (kh == 0) {
        const float4 o = *(const float4*)(red + t256 * 4);
        const float s[4] = {acc[0] + o.x, acc[1] + o.y, acc[2] + o.z, acc[3] + o.w};
        #pragma unroll
        for (int c = 0; c < 4; ++c) {
            float v = s[c] + bias[colBase + tx * 4 + c];
            if (relu) v = fmaxf(v, 0.0f);
            C[(size_t)(rowBase + ty) * ldb + colBase + tx * 4 + c] = v;
        }
    }
}

__global__ void __launch_bounds__(512, 1) k3_head1(const float* __restrict__ Wh1, const float* __restrict__ bh1) {
    head_gemm_splitk(g_G, Wh1, bh1, g_Z1, 1024, 512, true);
}
__global__ void __launch_bounds__(512, 1) k4_head2(const float* __restrict__ Wh2, const float* __restrict__ bh2) {
    head_gemm_splitk(g_Z1, Wh2, bh2, g_Z2, 512, 256, true);
}

// ---------------------------------------------------------------------------
// K5: raw = Z2 @ Wh3 + bh3 — warp per output, shfl reduce.
// ---------------------------------------------------------------------------
__global__ void k5_raw(const float* __restrict__ Wh3, const float* __restrict__ bh3)
{
    const int g = blockIdx.x * 8 + (threadIdx.x >> 5);
    if (g >= BATCH * 9) return;
    const int lane = threadIdx.x & 31;
    const int b = g / 9, j = g % 9;
    const float* z = g_Z2 + b * 256;
    float acc = 0.0f;
    #pragma unroll
    for (int i = 0; i < 8; ++i) {
        const int k = lane + i * 32;
        acc = fmaf(z[k], Wh3[k * 9 + j], acc);
    }
    #pragma unroll
    for (int off = 16; off > 0; off >>= 1)
        acc += __shfl_xor_sync(0xffffffffu, acc, off);
    if (lane == 0) g_RAW[g] = acc + bh3[j];
}

// ---------------------------------------------------------------------------
// K6: SVD projection onto SO(3). One thread per 3x3 matrix.
// ---------------------------------------------------------------------------
__device__ __forceinline__ void jrot(float A[3][3], float V[3][3], int p, int q)
{
    float apq = A[p][q];
    if (fabsf(apq) < 1e-20f) return;
    float tau = (A[q][q] - A[p][p]) / (2.0f * apq);
    float t = copysignf(1.0f, tau) / (fabsf(tau) + sqrtf(1.0f + tau * tau));
    float c = 1.0f / sqrtf(1.0f + t * t);
    float s = t * c;
    for (int r = 0; r < 3; ++r) {
        float arp = A[r][p], arq = A[r][q];
        A[r][p] = c * arp - s * arq;
        A[r][q] = s * arp + c * arq;
    }
    for (int r = 0; r < 3; ++r) {
        float apr = A[p][r], aqr = A[q][r];
        A[p][r] = c * apr - s * aqr;
        A[q][r] = s * apr + c * aqr;
    }
    for (int r = 0; r < 3; ++r) {
        float vrp = V[r][p], vrq = V[r][q];
        V[r][p] = c * vrp - s * vrq;
        V[r][q] = s * vrp + c * vrq;
    }
}

__global__ void k6_svd(float* __restrict__ out)
{
    int i = blockIdx.x * 32 + threadIdx.x;
    if (i >= BATCH) return;

    float M[3][3];
    for (int r = 0; r < 3; ++r)
        for (int c = 0; c < 3; ++c)
            M[r][c] = g_RAW[i * 9 + r * 3 + c];

    float A[3][3], V[3][3];
    for (int r = 0; r < 3; ++r)
        for (int c = 0; c < 3; ++c) {
            A[r][c] = M[0][r] * M[0][c] + M[1][r] * M[1][c] + M[2][r] * M[2][c];
            V[r][c] = (r == c) ? 1.0f : 0.0f;
        }

    for (int sweep = 0; sweep < 12; ++sweep) {
        jrot(A, V, 0, 1);
        jrot(A, V, 0, 2);
        jrot(A, V, 1, 2);
    }

    float e0 = A[0][0], e1 = A[1][1], e2 = A[2][2];
    int i0 = 0, i1 = 1, i2 = 2;
    if (e0 < e1) { float t = e0; e0 = e1; e1 = t; int ti = i0; i0 = i1; i1 = ti; }
    if (e0 < e2) { float t = e0; e0 = e2; e2 = t; int ti = i0; i0 = i2; i2 = ti; }
    if (e1 < e2) { float t = e1; e1 = e2; e2 = t; int ti = i1; i1 = i2; i2 = ti; }

    float v1[3], v2[3], v3[3];
    for (int r = 0; r < 3; ++r) { v1[r] = V[r][i0]; v2[r] = V[r][i1]; v3[r] = V[r][i2]; }

    float detV = v1[0] * (v2[1] * v3[2] - v2[2] * v3[1])
               - v1[1] * (v2[0] * v3[2] - v2[2] * v3[0])
               + v1[2] * (v2[0] * v3[1] - v2[1] * v3[0]);

    float w1[3], w2[3];
    for (int r = 0; r < 3; ++r) {
        w1[r] = M[r][0] * v1[0] + M[r][1] * v1[1] + M[r][2] * v1[2];
        w2[r] = M[r][0] * v2[0] + M[r][1] * v2[1] + M[r][2] * v2[2];
    }
    float n1 = sqrtf(w1[0] * w1[0] + w1[1] * w1[1] + w1[2] * w1[2] + 1e-30f);
    float u1[3] = { w1[0] / n1, w1[1] / n1, w1[2] / n1 };
    float d12 = u1[0] * w2[0] + u1[1] * w2[1] + u1[2] * w2[2];
    for (int r = 0; r < 3; ++r) w2[r] -= d12 * u1[r];
    float n2 = sqrtf(w2[0] * w2[0] + w2[1] * w2[1] + w2[2] * w2[2] + 1e-30f);
    float u2[3] = { w2[0] / n2, w2[1] / n2, w2[2] / n2 };
    float u3[3] = { u1[1] * u2[2] - u1[2] * u2[1],
                    u1[2] * u2[0] - u1[0] * u2[2],
                    u1[0] * u2[1] - u1[1] * u2[0] };
    if (detV < 0.0f) { u3[0] = -u3[0]; u3[1] = -u3[1]; u3[2] = -u3[2]; }

    for (int r = 0; r < 3; ++r)
        for (int c = 0; c < 3; ++c)
            out[i * 9 + r * 3 + c] = u1[r] * v1[c] + u2[r] * v2[c] + u3[r] * v3[c];
}

// ---------------------------------------------------------------------------
extern "C" void kernel_launch(void* const* d_in, const int* in_sizes, int n_in,
                              void* d_out, int out_size)
{
    const float* x   = (const float*)d_in[0];
    const float* W1  = (const float*)d_in[1];
    const float* b1  = (const float*)d_in[2];
    const float* W2  = (const float*)d_in[3];
    const float* b2  = (const float*)d_in[4];
    const float* W3  = (const float*)d_in[5];
    const float* b3  = (const float*)d_in[6];
    const float* Wh1 = (const float*)d_in[7];
    const float* bh1 = (const float*)d_in[8];
    const float* Wh2 = (const float*)d_in[9];
    const float* bh2 = (const float*)d_in[10];
    const float* Wh3 = (const float*)d_in[11];
    const float* bh3 = (const float*)d_in[12];
    float* out = (float*)d_out;

    cudaFuncSetAttribute(k1_point_mlp,  cudaFuncAttributeMaxDynamicSharedMemorySize, K1_SMEM);
    cudaFuncSetAttribute(k2_gemm_amax,  cudaFuncAttributeMaxDynamicSharedMemorySize, K2_SMEM);
    cudaFuncSetAttribute(k3_head1,      cudaFuncAttributeMaxDynamicSharedMemorySize, HD2_SMEM);
    cudaFuncSetAttribute(k4_head2,      cudaFuncAttributeMaxDynamicSharedMemorySize, HD2_SMEM);

    k1_point_mlp<<<2048, 512, K1_SMEM>>>(x, W1, b1, W2, b2);
    k2_gemm_amax<<<dim3(4, 256), 256, K2_SMEM>>>(W3);
    k2_fixup<<<dim3(4, 256), 256>>>(W3, b3);
    k3_head1<<<dim3(16, 8), 512, HD2_SMEM>>>(Wh1, bh1);
    k4_head2<<<dim3(16, 4), 512, HD2_SMEM>>>(Wh2, bh2);
    k5_raw<<<288, 256>>>(Wh3, bh3);
    k6_svd<<<8, 32>>>(out);

    (void)in_sizes; (void)n_in; (void)out_size;
}

// round 17
// speedup vs baseline: 2.0435x; 1.0067x over previous
#include <cuda_runtime.h>
#include <cuda_fp16.h>
#include <math.h>
#include <cstdint>

#define BATCH 256
#define NPTS  1024

// Scratch (device globals — allocation-free contract)
__device__ __half g_H2hi[BATCH * NPTS * 128];   // 64 MB
__device__ __half g_H2lo[BATCH * NPTS * 128];   // 64 MB
__device__ unsigned g_AMAX[BATCH * 1024];
__device__ float g_G[BATCH * 1024];
__device__ float g_Z1[BATCH * 512];
__device__ float g_Z2[BATCH * 256];

extern __shared__ char smem_raw[];

__device__ __forceinline__ uint32_t smem_u32(const void* p) {
    uint32_t a;
    asm("{ .reg .u64 t; cvta.to.shared.u64 t, %1; cvt.u32.u64 %0, t; }" : "=r"(a) : "l"(p));
    return a;
}

#define LDSM_X4(r0, r1, r2, r3, addr) \
    asm volatile("ldmatrix.sync.aligned.m8n8.x4.shared.b16 {%0,%1,%2,%3}, [%4];" \
                 : "=r"(r0), "=r"(r1), "=r"(r2), "=r"(r3) : "r"(addr))

__device__ __forceinline__ void mma_f16(float* d, const uint32_t* a, const uint32_t* b) {
    asm volatile("mma.sync.aligned.m16n8k16.row.col.f32.f16.f16.f32 "
                 "{%0,%1,%2,%3},{%4,%5,%6,%7},{%8,%9},{%0,%1,%2,%3};"
                 : "+f"(d[0]), "+f"(d[1]), "+f"(d[2]), "+f"(d[3])
                 : "r"(a[0]), "r"(a[1]), "r"(a[2]), "r"(a[3]), "r"(b[0]), "r"(b[1]));
}

// fp16-accumulate variant: D,C are 2 x .f16x2 regs (row r in d[0], row r+8 in d[1])
__device__ __forceinline__ void mma_f16acc(uint32_t* d, const uint32_t* a, const uint32_t* b) {
    asm volatile("mma.sync.aligned.m16n8k16.row.col.f16.f16.f16.f16 "
                 "{%0,%1},{%2,%3,%4,%5},{%6,%7},{%0,%1};"
                 : "+r"(d[0]), "+r"(d[1])
                 : "r"(a[0]), "r"(a[1]), "r"(a[2]), "r"(a[3]), "r"(b[0]), "r"(b[1]));
}

__device__ __forceinline__ uint32_t h2u(__half2 v) {
    uint32_t u; *(__half2*)&u = v; return u;
}

__device__ __forceinline__ void split2(float va, float vb, uint32_t& hi, uint32_t& lo) {
    __half2 h = __floats2half2_rn(va, vb);
    __half2 l = __floats2half2_rn(va - __half2float(__low2half(h)),
                                  vb - __half2float(__high2half(h)));
    hi = h2u(h); lo = h2u(l);
}

#define CP_ASYNC16(dst, src) \
    asm volatile("cp.async.cg.shared.global [%0], [%1], 16;" :: "r"(dst), "l"(src))
#define CP_COMMIT() asm volatile("cp.async.commit_group;" ::: "memory")
#define CP_WAIT(n)  asm volatile("cp.async.wait_group %0;" :: "n"(n) : "memory")

// ---------------------------------------------------------------------------
// K1: per-point MLP 3 -> 64 (scalar) -> 128 (HMMA fp16 3-combo hi/lo, fp32 acc),
// fused bias+ReLU+split epilogue, writes g_H2hi/g_H2lo.
// ---------------------------------------------------------------------------
#define K1_LDP 144
#define K1_A_HI 0
#define K1_A_LO 18432
#define K1_B_HI 36864
#define K1_B_LO 55296
#define K1_W1S  73728
#define K1_B1S  74496
#define K1_B2S  74752
#define K1_SMEM 75264

__global__ void __launch_bounds__(512, 1) k1_point_mlp(
    const float* __restrict__ x,
    const float* __restrict__ W1, const float* __restrict__ b1,
    const float* __restrict__ W2, const float* __restrict__ b2)
{
    char* sm = smem_raw;
    const uint32_t sb = smem_u32(sm);
    const int tid = threadIdx.x, lane = tid & 31, w = tid >> 5;
    const int wm = w & 3, wn = w >> 2;
    float* W1s = (float*)(sm + K1_W1S);
    float* b1s = (float*)(sm + K1_B1S);
    float* b2s = (float*)(sm + K1_B2S);

    for (int i = tid; i < 8192; i += 512) {
        const int n = i & 127, k = i >> 7;
        const float v = W2[k * 128 + n];
        const __half h = __float2half_rn(v);
        const __half l = __float2half_rn(v - __half2float(h));
        *(__half*)(sm + K1_B_HI + n * K1_LDP + k * 2) = h;
        *(__half*)(sm + K1_B_LO + n * K1_LDP + k * 2) = l;
    }
    if (tid < 192) W1s[tid] = W1[tid];
    else if (tid >= 256 && tid < 320) b1s[tid - 256] = b1[tid - 256];
    else if (tid >= 384 && tid < 512) b2s[tid - 384] = b2[tid - 384];
    __syncthreads();

    {
        const int pl = tid & 127;
        const int ks = (tid >> 7) * 16;
        const int pg = blockIdx.x * 128 + pl;
        const float x0 = x[pg * 3 + 0];
        const float x1 = x[pg * 3 + 1];
        const float x2 = x[pg * 3 + 2];
        #pragma unroll
        for (int kk = 0; kk < 16; kk += 2) {
            const int k = ks + kk;
            float va = fmaxf(fmaf(x0, W1s[k],     fmaf(x1, W1s[64 + k],     fmaf(x2, W1s[128 + k],     b1s[k]))), 0.0f);
            float vb = fmaxf(fmaf(x0, W1s[k + 1], fmaf(x1, W1s[64 + k + 1], fmaf(x2, W1s[128 + k + 1], b1s[k + 1]))), 0.0f);
            uint32_t hh, ll;
            split2(va, vb, hh, ll);
            *(uint32_t*)(sm + K1_A_HI + pl * K1_LDP + k * 2) = hh;
            *(uint32_t*)(sm + K1_A_LO + pl * K1_LDP + k * 2) = ll;
        }
    }
    __syncthreads();

    const uint32_t aRow = (uint32_t)(wm * 32 + (lane & 15));
    const uint32_t aCol = (uint32_t)((lane >> 4) * 16);
    const uint32_t aHi0 = sb + K1_A_HI + aRow * K1_LDP + aCol;
    const uint32_t aHi1 = aHi0 + 16 * K1_LDP;
    const uint32_t aLo0 = sb + K1_A_LO + aRow * K1_LDP + aCol;
    const uint32_t aLo1 = aLo0 + 16 * K1_LDP;
    const uint32_t bRow = (uint32_t)(wn * 32 + (lane & 7) + ((lane >> 4) << 3));
    const uint32_t bCol = (uint32_t)(((lane >> 3) & 1) * 16);
    const uint32_t bHi0 = sb + K1_B_HI + bRow * K1_LDP + bCol;
    const uint32_t bLo0 = sb + K1_B_LO + bRow * K1_LDP + bCol;

    float d[2][4][4];
    #pragma unroll
    for (int mt = 0; mt < 2; ++mt)
        #pragma unroll
        for (int j = 0; j < 4; ++j)
            #pragma unroll
            for (int c = 0; c < 4; ++c) d[mt][j][c] = 0.0f;

    #pragma unroll
    for (int ks = 0; ks < 4; ++ks) {
        const uint32_t ko = ks * 32;
        uint32_t aH0[4], aH1[4], aL0[4], aL1[4];
        LDSM_X4(aH0[0], aH0[1], aH0[2], aH0[3], aHi0 + ko);
        LDSM_X4(aH1[0], aH1[1], aH1[2], aH1[3], aHi1 + ko);
        LDSM_X4(aL0[0], aL0[1], aL0[2], aL0[3], aLo0 + ko);
        LDSM_X4(aL1[0], aL1[1], aL1[2], aL1[3], aLo1 + ko);
        #pragma unroll
        for (int j = 0; j < 2; ++j) {
            uint32_t bH[4], bL[4];
            LDSM_X4(bH[0], bH[1], bH[2], bH[3], bHi0 + j * (16 * K1_LDP) + ko);
            LDSM_X4(bL[0], bL[1], bL[2], bL[3], bLo0 + j * (16 * K1_LDP) + ko);
            mma_f16(d[0][2 * j],     aH0, bH);
            mma_f16(d[1][2 * j],     aH1, bH);
            mma_f16(d[0][2 * j + 1], aH0, bH + 2);
            mma_f16(d[1][2 * j + 1], aH1, bH + 2);
            mma_f16(d[0][2 * j],     aH0, bL);
            mma_f16(d[1][2 * j],     aH1, bL);
            mma_f16(d[0][2 * j + 1], aH0, bL + 2);
            mma_f16(d[1][2 * j + 1], aH1, bL + 2);
            mma_f16(d[0][2 * j],     aL0, bH);
            mma_f16(d[1][2 * j],     aL1, bH);
            mma_f16(d[0][2 * j + 1], aL0, bH + 2);
            mma_f16(d[1][2 * j + 1], aL1, bH + 2);
        }
    }

    const int pBase = blockIdx.x * 128;
    #pragma unroll
    for (int mt = 0; mt < 2; ++mt) {
        #pragma unroll
        for (int j = 0; j < 4; ++j) {
            const int col = wn * 32 + j * 8 + (lane & 3) * 2;
            const float bc0 = b2s[col], bc1 = b2s[col + 1];
            #pragma unroll
            for (int rr = 0; rr < 2; ++rr) {
                const int row = pBase + wm * 32 + mt * 16 + (lane >> 2) + rr * 8;
                const float v0 = fmaxf(d[mt][j][rr * 2 + 0] + bc0, 0.0f);
                const float v1 = fmaxf(d[mt][j][rr * 2 + 1] + bc1, 0.0f);
                uint32_t hh, ll;
                split2(v0, v1, hh, ll);
                *(uint32_t*)(g_H2hi + (size_t)row * 128 + col) = hh;
                *(uint32_t*)(g_H2lo + (size_t)row * 128 + col) = ll;
            }
        }
    }
}

// ---------------------------------------------------------------------------
// K2a: 1-combo fp16 HMMA (fp16 accumulate) + argmax-pool. Writes g_AMAX.
// 256 threads = 8 warps (2m x 4n), warp tile 32x64, cp.async double-buffered.
// ---------------------------------------------------------------------------
#define LDP 272
#define A_STAGE 17408                 // 64*272
#define OFF_A 0                       // 2 stages (hi only)
#define OFF_B 34816                   // 256*272
#define OFF_SV 104448                 // float[512]
#define OFF_SI 106496                 // uint[512]
#define K2_SMEM 108544

__global__ void __launch_bounds__(256, 2) k2_gemm_amax(const float* __restrict__ W3)
{
    char* sm = smem_raw;
    const uint32_t sb = smem_u32(sm);
    const int tid = threadIdx.x, lane = tid & 31, w = tid >> 5;
    const int wm = w & 1, wn = w >> 1;          // 2m x 4n
    const int b = blockIdx.y;
    const int colBase = blockIdx.x * 256;

    float* sval = (float*)(sm + OFF_SV);
    uint32_t* sidx = (uint32_t*)(sm + OFF_SI);

    const __half* srcHi = g_H2hi + (size_t)b * NPTS * 128;

    // tile 0 A-hi prefetch (overlaps B conversion fill)
    {
        const uint32_t dst = sb + OFF_A;
        #pragma unroll
        for (int i = 0; i < 4; ++i) {
            const int idx = tid + i * 256;
            const int m = idx >> 4, j = idx & 15;
            CP_ASYNC16(dst + m * LDP + j * 16, (const char*)srcHi + idx * 16);
        }
        CP_COMMIT();
    }

    // B fill: Bs[n][k] = fp16(W3[k][colBase+n]) (hi only)
    for (int idx = tid; idx < 32768; idx += 256) {
        const int n = idx & 255, k = idx >> 8;
        *(__half*)(sm + OFF_B + n * LDP + k * 2) = __float2half_rn(W3[k * 1024 + colBase + n]);
    }

    const uint32_t aRow = (uint32_t)(wm * 32 + (lane & 15));
    const uint32_t aCol = (uint32_t)((lane >> 4) * 16);
    const uint32_t aOff = aRow * LDP + aCol;
    const uint32_t bRow = (uint32_t)(wn * 64 + (lane & 7) + ((lane >> 4) << 3));
    const uint32_t bColB = (uint32_t)(((lane >> 3) & 1) * 16);
    const uint32_t bH0 = sb + OFF_B + bRow * LDP + bColB;

    float runmax[16];
    uint32_t runidx[16];
    #pragma unroll
    for (int i = 0; i < 16; ++i) { runmax[i] = -1e30f; runidx[i] = 0; }

    for (int t = 0; t < 16; ++t) {
        if (t < 15) {
            const uint32_t dst = sb + OFF_A + ((t + 1) & 1) * A_STAGE;
            const int base = (t + 1) * 1024;
            #pragma unroll
            for (int i = 0; i < 4; ++i) {
                const int idx = tid + i * 256;
                const int m = idx >> 4, j = idx & 15;
                CP_ASYNC16(dst + m * LDP + j * 16, (const char*)srcHi + (base + idx) * 16);
            }
            CP_COMMIT();
            CP_WAIT(1);
        } else {
            CP_WAIT(0);
        }
        __syncthreads();

        const uint32_t aHi0 = sb + OFF_A + (t & 1) * A_STAGE + aOff;

        uint32_t dd[2][8][2];     // fp16x2 accumulators: [mt][ntile][row r / r+8]
        #pragma unroll
        for (int mt = 0; mt < 2; ++mt)
            #pragma unroll
            for (int j = 0; j < 8; ++j) { dd[mt][j][0] = 0u; dd[mt][j][1] = 0u; }

        #pragma unroll
        for (int ks = 0; ks < 8; ++ks) {
            const uint32_t ko = ks * 32;
            uint32_t aH0[4], aH1[4];
            LDSM_X4(aH0[0], aH0[1], aH0[2], aH0[3], aHi0 + ko);
            LDSM_X4(aH1[0], aH1[1], aH1[2], aH1[3], aHi0 + 16 * LDP + ko);
            #pragma unroll
            for (int j = 0; j < 4; ++j) {
                uint32_t bH[4];
                LDSM_X4(bH[0], bH[1], bH[2], bH[3], bH0 + j * (16 * LDP) + ko);
                mma_f16acc(dd[0][2 * j],     aH0, bH);
                mma_f16acc(dd[1][2 * j],     aH1, bH);
                mma_f16acc(dd[0][2 * j + 1], aH0, bH + 2);
                mma_f16acc(dd[1][2 * j + 1], aH1, bH + 2);
            }
        }

        // fold (max, argmax): candidate rows = rbase + {0,8,16,24}
        const uint32_t rbase = (uint32_t)(t * 64 + wm * 32 + (lane >> 2));
        #pragma unroll
        for (int f = 0; f < 8; ++f) {
            const float2 rA = __half22float2(*(const __half2*)&dd[0][f][0]); // row r
            const float2 rB = __half22float2(*(const __half2*)&dd[0][f][1]); // row r+8
            const float2 rC = __half22float2(*(const __half2*)&dd[1][f][0]); // row r+16
            const float2 rD = __half22float2(*(const __half2*)&dd[1][f][1]); // row r+24
            #pragma unroll
            for (int cc = 0; cc < 2; ++cc) {
                const int e = f * 2 + cc;
                const float v0 = cc ? rA.y : rA.x;
                const float v1 = cc ? rB.y : rB.x;
                const float v2 = cc ? rC.y : rC.x;
                const float v3 = cc ? rD.y : rD.x;
                if (v0 > runmax[e]) { runmax[e] = v0; runidx[e] = rbase; }
                if (v1 > runmax[e]) { runmax[e] = v1; runidx[e] = rbase + 8; }
                if (v2 > runmax[e]) { runmax[e] = v2; runidx[e] = rbase + 16; }
                if (v3 > runmax[e]) { runmax[e] = v3; runidx[e] = rbase + 24; }
            }
        }
        __syncthreads();
    }

    // cross-lane (row lives in lane bits 2..4): reduce val+idx
    #pragma unroll
    for (int e = 0; e < 16; ++e) {
        #pragma unroll
        for (int off = 4; off <= 16; off <<= 1) {
            const float ov = __shfl_xor_sync(0xffffffffu, runmax[e], off);
            const uint32_t oi = __shfl_xor_sync(0xffffffffu, runidx[e], off);
            if (ov > runmax[e]) { runmax[e] = ov; runidx[e] = oi; }
        }
    }
    if (lane < 4) {
        #pragma unroll
        for (int f = 0; f < 8; ++f) {
            #pragma unroll
            for (int cc = 0; cc < 2; ++cc) {
                const int cl = wn * 64 + f * 8 + lane * 2 + cc;
                sval[wm * 256 + cl] = runmax[f * 2 + cc];
                sidx[wm * 256 + cl] = runidx[f * 2 + cc];
            }
        }
    }
    __syncthreads();
    {
        const float v0 = sval[tid], v1 = sval[256 + tid];
        g_AMAX[b * 1024 + colBase + tid] = (v1 > v0) ? sidx[256 + tid] : sidx[tid];
    }
}

// ---------------------------------------------------------------------------
// K2b: exact fixup. g[b][col] = relu(fp32 dot(h2[argmax], W3[:,col]) + b3).
// 512-thread CTAs, grid (2, 256): each thread handles one column.
// ---------------------------------------------------------------------------
__global__ void __launch_bounds__(512) k2_fixup(const float* __restrict__ W3,
                                                const float* __restrict__ b3)
{
    const int tid = threadIdx.x;
    const int b = blockIdx.y;
    const int col = blockIdx.x * 512 + tid;
    const unsigned i = g_AMAX[b * 1024 + col];

    const uint4* hi = (const uint4*)(g_H2hi + ((size_t)b * NPTS + i) * 128);
    const uint4* lo = (const uint4*)(g_H2lo + ((size_t)b * NPTS + i) * 128);

    float acc = 0.0f;
    #pragma unroll
    for (int c = 0; c < 16; ++c) {
        const uint4 h4 = hi[c];
        const uint4 l4 = lo[c];
        const uint32_t hw[4] = {h4.x, h4.y, h4.z, h4.w};
        const uint32_t lw[4] = {l4.x, l4.y, l4.z, l4.w};
        #pragma unroll
        for (int q = 0; q < 4; ++q) {
            const __half2 hh = *(const __half2*)&hw[q];
            const __half2 ll = *(const __half2*)&lw[q];
            const int k = c * 8 + q * 2;
            const float a0 = __half2float(__low2half(hh))  + __half2float(__low2half(ll));
            const float a1 = __half2float(__high2half(hh)) + __half2float(__high2half(ll));
            acc = fmaf(a0, W3[(size_t)k * 1024 + col], acc);
            acc = fmaf(a1, W3[(size_t)(k + 1) * 1024 + col], acc);
        }
    }
    g_G[b * 1024 + col] = fmaxf(acc + b3[col], 0.0f);
}

// ---------------------------------------------------------------------------
// Head GEMMs: 16x64 tile, split-K x2 (512 threads), 2-stage cp.async per half.
// ---------------------------------------------------------------------------
#define HD2_AS 1088    // 16*68 floats
#define HD2_BS 4096    // 64*64 floats
#define HD2_STAGE (HD2_AS + HD2_BS)
#define HD2_SMEM (4 * HD2_STAGE * 4)   // 2 halves x 2 stages

__device__ __forceinline__ void hd2_load_chunk(
    uint32_t as, uint32_t bs,
    const float* __restrict__ A, const float* __restrict__ B,
    int rowBase, int colBase, int K, int ldb, int k0, int t256)
{
    {
        const int r = t256 >> 4, k = (t256 & 15) * 4;
        CP_ASYNC16(as + (r * 68 + k) * 4, A + (size_t)(rowBase + r) * K + k0 + k);
    }
    #pragma unroll
    for (int i = 0; i < 4; ++i) {
        const int idx = t256 + i * 256;
        const int r = idx >> 4, c = (idx & 15) * 4;
        CP_ASYNC16(bs + (r * 64 + c) * 4, B + (size_t)(k0 + r) * ldb + colBase + c);
    }
}

__device__ __forceinline__ void head_gemm_splitk(
    const float* __restrict__ A, const float* __restrict__ B,
    const float* __restrict__ bias, float* __restrict__ C,
    int K, int ldb, bool relu)
{
    float* sm = (float*)smem_raw;
    const uint32_t sb = smem_u32(sm);
    const int tid = threadIdx.x;
    const int kh = tid >> 8;            // k-half 0/1
    const int t256 = tid & 255;
    const int tx = t256 & 15, ty = t256 >> 4;
    const int rowBase = blockIdx.x * 16;
    const int colBase = blockIdx.y * 64;
    const int nCh = K >> 7;             // chunks of 64 per half
    const int kBase = kh * (K >> 1);
    const uint32_t stage0 = sb + (2 * kh) * HD2_STAGE * 4;
    const uint32_t stage1 = sb + (2 * kh + 1) * HD2_STAGE * 4;

    hd2_load_chunk(stage0, stage0 + HD2_AS * 4, A, B, rowBase, colBase, K, ldb, kBase, t256);
    CP_COMMIT();

    float acc[4] = {0.0f, 0.0f, 0.0f, 0.0f};

    for (int ch = 0; ch < nCh; ++ch) {
        if (ch + 1 < nCh) {
            const uint32_t as = (ch + 1) & 1 ? stage1 : stage0;
            hd2_load_chunk(as, as + HD2_AS * 4, A, B, rowBase, colBase, K, ldb,
                           kBase + (ch + 1) * 64, t256);
            CP_COMMIT();
            CP_WAIT(1);
        } else {
            CP_WAIT(0);
        }
        __syncthreads();

        const float* As = sm + ((2 * kh + (ch & 1)) * HD2_STAGE);
        const float* Bs = As + HD2_AS;

        #pragma unroll 16
        for (int k = 0; k < 64; ++k) {
            const float4 wv = *(const float4*)(Bs + k * 64 + tx * 4);
            const float a0 = As[ty * 68 + k];
            acc[0] = fmaf(a0, wv.x, acc[0]); acc[1] = fmaf(a0, wv.y, acc[1]);
            acc[2] = fmaf(a0, wv.z, acc[2]); acc[3] = fmaf(a0, wv.w, acc[3]);
        }
        __syncthreads();
    }

    float* red = sm;
    if (kh == 1) {
        *(float4*)(red + t256 * 4) = make_float4(acc[0], acc[1], acc[2], acc[3]);
    }
    __syncthreads();
    if (kh == 0) {
        const float4 o = *(const float4*)(red + t256 * 4);
        const float s[4] = {acc[0] + o.x, acc[1] + o.y, acc[2] + o.z, acc[3] + o.w};
        #pragma unroll
        for (int c = 0; c < 4; ++c) {
            float v = s[c] + bias[colBase + tx * 4 + c];
            if (relu) v = fmaxf(v, 0.0f);
            C[(size_t)(rowBase + ty) * ldb + colBase + tx * 4 + c] = v;
        }
    }
}

__global__ void __launch_bounds__(512, 1) k3_head1(const float* __restrict__ Wh1, const float* __restrict__ bh1) {
    head_gemm_splitk(g_G, Wh1, bh1, g_Z1, 1024, 512, true);
}
__global__ void __launch_bounds__(512, 1) k4_head2(const float* __restrict__ Wh2, const float* __restrict__ bh2) {
    head_gemm_splitk(g_Z1, Wh2, bh2, g_Z2, 512, 256, true);
}

// ---------------------------------------------------------------------------
// K56 (fused): one CTA per batch (288 threads = 9 warps). Warp j computes
// raw[j] = dot(Z2[b], Wh3[:,j]) + bh3[j] via shfl reduce into smem; thread 0
// then runs the 3x3 Jacobi SVD projection and writes out[b].
// ---------------------------------------------------------------------------
__device__ __forceinline__ void jrot(float A[3][3], float V[3][3], int p, int q)
{
    float apq = A[p][q];
    if (fabsf(apq) < 1e-20f) return;
    float tau = (A[q][q] - A[p][p]) / (2.0f * apq);
    float t = copysignf(1.0f, tau) / (fabsf(tau) + sqrtf(1.0f + tau * tau));
    float c = 1.0f / sqrtf(1.0f + t * t);
    float s = t * c;
    for (int r = 0; r < 3; ++r) {
        float arp = A[r][p], arq = A[r][q];
        A[r][p] = c * arp - s * arq;
        A[r][q] = s * arp + c * arq;
    }
    for (int r = 0; r < 3; ++r) {
        float apr = A[p][r], aqr = A[q][r];
        A[p][r] = c * apr - s * aqr;
        A[q][r] = s * apr + c * aqr;
    }
    for (int r = 0; r < 3; ++r) {
        float vrp = V[r][p], vrq = V[r][q];
        V[r][p] = c * vrp - s * vrq;
        V[r][q] = s * vrp + c * vrq;
    }
}

__global__ void __launch_bounds__(288) k56_raw_svd(
    const float* __restrict__ Wh3, const float* __restrict__ bh3,
    float* __restrict__ out)
{
    __shared__ float raw[9];
    const int b = blockIdx.x;
    const int w = threadIdx.x >> 5;     // 0..8
    const int lane = threadIdx.x & 31;

    // stage 1: 9 warps, one output each
    {
        const float* z = g_Z2 + b * 256;
        float acc = 0.0f;
        #pragma unroll
        for (int i = 0; i < 8; ++i) {
            const int k = lane + i * 32;
            acc = fmaf(z[k], Wh3[k * 9 + w], acc);
        }
        #pragma unroll
        for (int off = 16; off > 0; off >>= 1)
            acc += __shfl_xor_sync(0xffffffffu, acc, off);
        if (lane == 0) raw[w] = acc + bh3[w];
    }
    __syncthreads();

    // stage 2: thread 0 does the 3x3 SVD projection
    if (threadIdx.x == 0) {
        float M[3][3];
        for (int r = 0; r < 3; ++r)
            for (int c = 0; c < 3; ++c)
                M[r][c] = raw[r * 3 + c];

        float A[3][3], V[3][3];
        for (int r = 0; r < 3; ++r)
            for (int c = 0; c < 3; ++c) {
                A[r][c] = M[0][r] * M[0][c] + M[1][r] * M[1][c] + M[2][r] * M[2][c];
                V[r][c] = (r == c) ? 1.0f : 0.0f;
            }

        for (int sweep = 0; sweep < 12; ++sweep) {
            jrot(A, V, 0, 1);
            jrot(A, V, 0, 2);
            jrot(A, V, 1, 2);
        }

        float e0 = A[0][0], e1 = A[1][1], e2 = A[2][2];
        int i0 = 0, i1 = 1, i2 = 2;
        if (e0 < e1) { float t = e0; e0 = e1; e1 = t; int ti = i0; i0 = i1; i1 = ti; }
        if (e0 < e2) { float t = e0; e0 = e2; e2 = t; int ti = i0; i0 = i2; i2 = ti; }
        if (e1 < e2) { float t = e1; e1 = e2; e2 = t; int ti = i1; i1 = i2; i2 = ti; }

        float v1[3], v2[3], v3[3];
        for (int r = 0; r < 3; ++r) { v1[r] = V[r][i0]; v2[r] = V[r][i1]; v3[r] = V[r][i2]; }

        float detV = v1[0] * (v2[1] * v3[2] - v2[2] * v3[1])
                   - v1[1] * (v2[0] * v3[2] - v2[2] * v3[0])
                   + v1[2] * (v2[0] * v3[1] - v2[1] * v3[0]);

        float w1[3], w2[3];
        for (int r = 0; r < 3; ++r) {
            w1[r] = M[r][0] * v1[0] + M[r][1] * v1[1] + M[r][2] * v1[2];
            w2[r] = M[r][0] * v2[0] + M[r][1] * v2[1] + M[r][2] * v2[2];
        }
        float n1 = sqrtf(w1[0] * w1[0] + w1[1] * w1[1] + w1[2] * w1[2] + 1e-30f);
        float u1[3] = { w1[0] / n1, w1[1] / n1, w1[2] / n1 };
        float d12 = u1[0] * w2[0] + u1[1] * w2[1] + u1[2] * w2[2];
        for (int r = 0; r < 3; ++r) w2[r] -= d12 * u1[r];
        float n2 = sqrtf(w2[0] * w2[0] + w2[1] * w2[1] + w2[2] * w2[2] + 1e-30f);
        float u2[3] = { w2[0] / n2, w2[1] / n2, w2[2] / n2 };
        float u3[3] = { u1[1] * u2[2] - u1[2] * u2[1],
                        u1[2] * u2[0] - u1[0] * u2[2],
                        u1[0] * u2[1] - u1[1] * u2[0] };
        if (detV < 0.0f) { u3[0] = -u3[0]; u3[1] = -u3[1]; u3[2] = -u3[2]; }

        for (int r = 0; r < 3; ++r)
            for (int c = 0; c < 3; ++c)
                out[b * 9 + r * 3 + c] = u1[r] * v1[c] + u2[r] * v2[c] + u3[r] * v3[c];
    }
}

// ---------------------------------------------------------------------------
extern "C" void kernel_launch(void* const* d_in, const int* in_sizes, int n_in,
                              void* d_out, int out_size)
{
    const float* x   = (const float*)d_in[0];
    const float* W1  = (const float*)d_in[1];
    const float* b1  = (const float*)d_in[2];
    const float* W2  = (const float*)d_in[3];
    const float* b2  = (const float*)d_in[4];
    const float* W3  = (const float*)d_in[5];
    const float* b3  = (const float*)d_in[6];
    const float* Wh1 = (const float*)d_in[7];
    const float* bh1 = (const float*)d_in[8];
    const float* Wh2 = (const float*)d_in[9];
    const float* bh2 = (const float*)d_in[10];
    const float* Wh3 = (const float*)d_in[11];
    const float* bh3 = (const float*)d_in[12];
    float* out = (float*)d_out;

    cudaFuncSetAttribute(k1_point_mlp,  cudaFuncAttributeMaxDynamicSharedMemorySize, K1_SMEM);
    cudaFuncSetAttribute(k2_gemm_amax,  cudaFuncAttributeMaxDynamicSharedMemorySize, K2_SMEM);
    cudaFuncSetAttribute(k3_head1,      cudaFuncAttributeMaxDynamicSharedMemorySize, HD2_SMEM);
    cudaFuncSetAttribute(k4_head2,      cudaFuncAttributeMaxDynamicSharedMemorySize, HD2_SMEM);

    k1_point_mlp<<<2048, 512, K1_SMEM>>>(x, W1, b1, W2, b2);
    k2_gemm_amax<<<dim3(4, 256), 256, K2_SMEM>>>(W3);
    k2_fixup<<<dim3(2, 256), 512>>>(W3, b3);
    k3_head1<<<dim3(16, 8), 512, HD2_SMEM>>>(Wh1, bh1);
    k4_head2<<<dim3(16, 4), 512, HD2_SMEM>>>(Wh2, bh2);
    k56_raw_svd<<<256, 288>>>(Wh3, bh3, out);

    (void)in_sizes; (void)n_in; (void)out_size;
}